// round 1
// baseline (speedup 1.0000x reference)
#include <cuda_runtime.h>
#include <cuda_bf16.h>
#include <stdint.h>
#include <math.h>

#define NROWS 8192
#define DIM   512
#define TM    128
#define TN    128
#define KT    64
#define APAD  520   // bf16 elems per A smem row (conflict-free: 520*2/4 % 32 == 4)
#define BPAD  72    // bf16 elems per B smem row
#define COLSPLIT 4
#define COLS_PER_CTA (NROWS / COLSPLIT)   // 2048
#define NCHUNKS (COLS_PER_CTA / TN)       // 16
#define SMEM_BYTES ((TM*APAD + 2*TN*BPAD) * 2)  // 169,984 B

// ---------------- device scratch (no allocations allowed) ----------------
__device__ __align__(256) float          g_x [NROWS * DIM];  // normalized fp32
__device__ __align__(256) __nv_bfloat16  g_xh[NROWS * DIM];  // normalized bf16
__device__ unsigned long long            g_best[NROWS];      // packed (orderkey<<32)|idx
__device__ float                         g_log[NROWS];

// order-preserving float->uint key
__device__ __forceinline__ unsigned long long pack_vi(float v, int i) {
    unsigned u = __float_as_uint(v);
    u = (u & 0x80000000u) ? ~u : (u | 0x80000000u);
    return ((unsigned long long)u << 32) | (unsigned)i;
}

// ---------------- 1) normalize rows, reset argmax buffer ----------------
__global__ void norm_kernel(const float* __restrict__ in) {
    int row = blockIdx.x;
    int tid = threadIdx.x;            // 128 threads, 4 floats each
    if (tid == 0) g_best[row] = 0ull; // below every real key
    float4 v = ((const float4*)(in + (size_t)row * DIM))[tid];
    float s = v.x*v.x + v.y*v.y + v.z*v.z + v.w*v.w;
    #pragma unroll
    for (int o = 16; o; o >>= 1) s += __shfl_xor_sync(0xffffffffu, s, o);
    __shared__ float ws[4];
    if ((tid & 31) == 0) ws[tid >> 5] = s;
    __syncthreads();
    float tot = ws[0] + ws[1] + ws[2] + ws[3];
    float inv = 1.0f / fmaxf(sqrtf(tot), 1e-8f);
    float4 o4 = make_float4(v.x*inv, v.y*inv, v.z*inv, v.w*inv);
    ((float4*)(g_x + (size_t)row * DIM))[tid] = o4;
    __nv_bfloat162* hp = (__nv_bfloat162*)(g_xh + (size_t)row * DIM);
    hp[tid*2+0] = __floats2bfloat162_rn(o4.x, o4.y);
    hp[tid*2+1] = __floats2bfloat162_rn(o4.z, o4.w);
}

// ---------------- 2) fused bf16 GEMM + argmax ----------------
__device__ __forceinline__ void mma16816(float* c, const uint32_t* a, const uint32_t* b) {
    asm volatile(
        "mma.sync.aligned.m16n8k16.row.col.f32.bf16.bf16.f32 "
        "{%0,%1,%2,%3}, {%4,%5,%6,%7}, {%8,%9}, {%0,%1,%2,%3};\n"
        : "+f"(c[0]), "+f"(c[1]), "+f"(c[2]), "+f"(c[3])
        : "r"(a[0]), "r"(a[1]), "r"(a[2]), "r"(a[3]), "r"(b[0]), "r"(b[1]));
}

__global__ __launch_bounds__(256, 1) void gemm_argmax_kernel() {
    extern __shared__ __nv_bfloat16 sm[];
    __nv_bfloat16* As = sm;                 // [128][APAD], full K resident
    __nv_bfloat16* Bs = sm + TM * APAD;     // [2][128][BPAD], 64-k slabs

    const int tid  = threadIdx.x;
    const int lane = tid & 31, warp = tid >> 5;
    const int wm = warp >> 1, wn = warp & 1;      // 4x2 warp grid
    const int rowbase    = blockIdx.x * TM;
    const int colCTAbase = blockIdx.y * COLS_PER_CTA;
    const int lrow = lane >> 2, lk2 = (lane & 3) * 2;

    // Load A tile (128x512 bf16) once, padded layout
    {
        const uint2* src = (const uint2*)(g_xh + (size_t)rowbase * DIM);
        #pragma unroll 4
        for (int i = tid; i < TM * DIM / 4; i += 256) {
            uint2 d = src[i];
            int r = i >> 7;              // 128 uint2 per row
            int c = (i & 127) * 4;
            *(uint2*)(As + r * APAD + c) = d;
        }
    }
    __syncthreads();

    float rbv[2][2];
    int   rbi[2][2];
    #pragma unroll
    for (int mf = 0; mf < 2; mf++)
        #pragma unroll
        for (int h = 0; h < 2; h++) { rbv[mf][h] = -1e30f; rbi[mf][h] = 0; }

    float acc[2][8][4];
    uint2 pre[8];

    for (int nj = 0; nj < NCHUNKS; nj++) {
        const int colbase = colCTAbase + nj * TN;
        #pragma unroll
        for (int mf = 0; mf < 2; mf++)
            #pragma unroll
            for (int nf = 0; nf < 8; nf++)
                #pragma unroll
                for (int e = 0; e < 4; e++) acc[mf][nf][e] = 0.0f;

        // slab 0 direct
        #pragma unroll
        for (int i = 0; i < 8; i++) {
            int linear = i * 1024 + tid * 4;
            int c = linear >> 6, k = linear & 63;
            *(uint2*)(Bs + c * BPAD + k) =
                *(const uint2*)(g_xh + (size_t)(colbase + c) * DIM + k);
        }
        __syncthreads();

        #pragma unroll 1
        for (int kk = 0; kk < 8; kk++) {
            const int buf = kk & 1;
            if (kk < 7) {
                const int kg = (kk + 1) * KT;
                #pragma unroll
                for (int i = 0; i < 8; i++) {
                    int linear = i * 1024 + tid * 4;
                    int c = linear >> 6, k = linear & 63;
                    pre[i] = *(const uint2*)(g_xh + (size_t)(colbase + c) * DIM + kg + k);
                }
            }
            #pragma unroll
            for (int ks = 0; ks < 4; ks++) {
                const int kA = kk * KT + ks * 16;
                const int kB = ks * 16;
                uint32_t a[2][4], b[8][2];
                #pragma unroll
                for (int mf = 0; mf < 2; mf++) {
                    const __nv_bfloat16* p = As + (wm*32 + mf*16 + lrow) * APAD + kA + lk2;
                    a[mf][0] = *(const uint32_t*)p;
                    a[mf][1] = *(const uint32_t*)(p + 8 * APAD);
                    a[mf][2] = *(const uint32_t*)(p + 8);
                    a[mf][3] = *(const uint32_t*)(p + 8 * APAD + 8);
                }
                #pragma unroll
                for (int nf = 0; nf < 8; nf++) {
                    const __nv_bfloat16* p = Bs + buf * TN * BPAD +
                                             (wn*64 + nf*8 + lrow) * BPAD + kB + lk2;
                    b[nf][0] = *(const uint32_t*)p;
                    b[nf][1] = *(const uint32_t*)(p + 8);
                }
                #pragma unroll
                for (int mf = 0; mf < 2; mf++)
                    #pragma unroll
                    for (int nf = 0; nf < 8; nf++)
                        mma16816(acc[mf][nf], a[mf], b[nf]);
            }
            if (kk < 7) {
                __syncthreads();
                const int nbuf = (kk + 1) & 1;
                #pragma unroll
                for (int i = 0; i < 8; i++) {
                    int linear = i * 1024 + tid * 4;
                    int c = linear >> 6, k = linear & 63;
                    *(uint2*)(Bs + nbuf * TN * BPAD + c * BPAD + k) = pre[i];
                }
                __syncthreads();
            }
        }

        // fold this 128x128 tile into running argmax (mask diagonal)
        #pragma unroll
        for (int mf = 0; mf < 2; mf++)
            #pragma unroll
            for (int h = 0; h < 2; h++) {
                const int grow = rowbase + wm*32 + mf*16 + lrow + h*8;
                float bv = rbv[mf][h]; int bi = rbi[mf][h];
                #pragma unroll
                for (int nf = 0; nf < 8; nf++) {
                    const int c0 = colbase + wn*64 + nf*8 + lk2;
                    const float v0 = acc[mf][nf][h*2+0];
                    const float v1 = acc[mf][nf][h*2+1];
                    if (c0     != grow && v0 > bv) { bv = v0; bi = c0;     }
                    if (c0 + 1 != grow && v1 > bv) { bv = v1; bi = c0 + 1; }
                }
                rbv[mf][h] = bv; rbi[mf][h] = bi;
            }
    }

    // reduce the 4 lanes sharing each row, then merge chip-wide
    #pragma unroll
    for (int mf = 0; mf < 2; mf++)
        #pragma unroll
        for (int h = 0; h < 2; h++) {
            float bv = rbv[mf][h]; int bi = rbi[mf][h];
            #pragma unroll
            for (int o = 1; o < 4; o <<= 1) {
                float ov = __shfl_xor_sync(0xffffffffu, bv, o);
                int   oi = __shfl_xor_sync(0xffffffffu, bi, o);
                if (ov > bv) { bv = ov; bi = oi; }
            }
            if ((lane & 3) == 0) {
                const int grow = rowbase + wm*32 + mf*16 + lrow + h*8;
                atomicMax(&g_best[grow], pack_vi(bv, bi));
            }
        }
}

// ---------------- 3) per-row NN distance (fp32 exact) ----------------
__global__ void dist_kernel() {
    int row = blockIdx.x;
    int tid = threadIdx.x;   // 128 threads
    int j = (int)(g_best[row] & 0xffffffffull);
    float4 a = ((const float4*)(g_x + (size_t)row * DIM))[tid];
    float4 b = ((const float4*)(g_x + (size_t)j   * DIM))[tid];
    float dx = a.x - b.x + 1e-8f;
    float dy = a.y - b.y + 1e-8f;
    float dz = a.z - b.z + 1e-8f;
    float dw = a.w - b.w + 1e-8f;
    float s = dx*dx + dy*dy + dz*dz + dw*dw;
    #pragma unroll
    for (int o = 16; o; o >>= 1) s += __shfl_xor_sync(0xffffffffu, s, o);
    __shared__ float ws[4];
    if ((tid & 31) == 0) ws[tid >> 5] = s;
    __syncthreads();
    if (tid == 0) {
        float tot = ws[0] + ws[1] + ws[2] + ws[3];
        g_log[row] = logf(sqrtf(tot) + 1e-8f);
    }
}

// ---------------- 4) deterministic final reduce ----------------
__global__ void reduce_kernel(float* __restrict__ out) {
    int tid = threadIdx.x;   // 1024 threads
    float s = 0.0f;
    #pragma unroll
    for (int i = 0; i < NROWS / 1024; i++) s += g_log[tid + i * 1024];
    #pragma unroll
    for (int o = 16; o; o >>= 1) s += __shfl_xor_sync(0xffffffffu, s, o);
    __shared__ float ws[32];
    if ((tid & 31) == 0) ws[tid >> 5] = s;
    __syncthreads();
    if (tid < 32) {
        float v = ws[tid];
        #pragma unroll
        for (int o = 16; o; o >>= 1) v += __shfl_xor_sync(0xffffffffu, v, o);
        if (tid == 0) out[0] = -v / (float)NROWS;
    }
}

extern "C" void kernel_launch(void* const* d_in, const int* in_sizes, int n_in,
                              void* d_out, int out_size) {
    const float* in = (const float*)d_in[0];
    float* out = (float*)d_out;
    (void)in_sizes; (void)n_in; (void)out_size;

    cudaFuncSetAttribute((const void*)gemm_argmax_kernel,
                         cudaFuncAttributeMaxDynamicSharedMemorySize, SMEM_BYTES);

    norm_kernel<<<NROWS, 128>>>(in);
    gemm_argmax_kernel<<<dim3(NROWS / TM, COLSPLIT), 256, SMEM_BYTES>>>();
    dist_kernel<<<NROWS, 128>>>();
    reduce_kernel<<<1, 1024>>>(out);
}